// round 9
// baseline (speedup 1.0000x reference)
#include <cuda_runtime.h>
#include <math.h>

// ---------------- Problem constants ----------------
#define BB   2
#define TT   4
#define HWN  1024            // H*W
#define TKV  4096            // T*H*W
#define DQ   768             // DINO_DIM
#define CK   1920            // COG_DIM
#define NH   12
#define HD   64
#define MQ   (BB*HWN)        // 2048 query rows
#define MKV  (BB*TKV)        // 8192 kv rows

// ---------------- Scratch (device globals; no allocation APIs) ----------------
__device__ float g_xq [MQ  * DQ];          //  6.3 MB  normalized q input
__device__ float g_xkv[MKV * CK];          // 62.9 MB  normalized kv input
__device__ float g_q  [MQ  * DQ];          //  6.3 MB
__device__ float g_k  [MKV * DQ];          // 25.2 MB
__device__ float g_v  [MKV * DQ];          // 25.2 MB
__device__ float g_s  [(size_t)BB*NH*HWN*TKV]; // 402.7 MB attention scores / probs
__device__ float g_att[MQ  * DQ];          //  6.3 MB

// ---------------- LayerNorm for q path: input [B, 768, 32, 32] ----------------
__global__ __launch_bounds__(256) void ln_q_kernel(const float* __restrict__ x,
                                                   const float* __restrict__ g,
                                                   const float* __restrict__ be)
{
    int row = blockIdx.x;            // 0..2047 = b*1024 + pix
    int b   = row >> 10;
    int pix = row & 1023;
    const float* base = x + (size_t)b * DQ * HWN + pix;   // stride HWN over channels

    __shared__ float sbuf[DQ];
    __shared__ float red[256];
    int tid = threadIdx.x;

    float s = 0.f;
    for (int c = tid; c < DQ; c += 256) {
        float v = base[(size_t)c * HWN];
        sbuf[c] = v;
        s += v;
    }
    red[tid] = s; __syncthreads();
    for (int st = 128; st > 0; st >>= 1) { if (tid < st) red[tid] += red[tid + st]; __syncthreads(); }
    float mu = red[0] * (1.f / DQ);
    __syncthreads();

    float s2 = 0.f;
    for (int c = tid; c < DQ; c += 256) { float d = sbuf[c] - mu; s2 += d * d; }
    red[tid] = s2; __syncthreads();
    for (int st = 128; st > 0; st >>= 1) { if (tid < st) red[tid] += red[tid + st]; __syncthreads(); }
    float rstd = rsqrtf(red[0] * (1.f / DQ) + 1e-5f);

    float* out = g_xq + (size_t)row * DQ;
    for (int c = tid; c < DQ; c += 256)
        out[c] = (sbuf[c] - mu) * rstd * g[c] + be[c];
}

// ---------------- LayerNorm for kv path: input [B,T,H,W,1920] ----------------
__global__ __launch_bounds__(256) void ln_kv_kernel(const float* __restrict__ x,
                                                    const float* __restrict__ g,
                                                    const float* __restrict__ be)
{
    int row = blockIdx.x;            // 0..8191
    const float* base = x + (size_t)row * CK;

    __shared__ float sbuf[CK];
    __shared__ float red[256];
    int tid = threadIdx.x;

    float s = 0.f;
    for (int c = tid; c < CK; c += 256) { float v = base[c]; sbuf[c] = v; s += v; }
    red[tid] = s; __syncthreads();
    for (int st = 128; st > 0; st >>= 1) { if (tid < st) red[tid] += red[tid + st]; __syncthreads(); }
    float mu = red[0] * (1.f / CK);
    __syncthreads();

    float s2 = 0.f;
    for (int c = tid; c < CK; c += 256) { float d = sbuf[c] - mu; s2 += d * d; }
    red[tid] = s2; __syncthreads();
    for (int st = 128; st > 0; st >>= 1) { if (tid < st) red[tid] += red[tid + st]; __syncthreads(); }
    float rstd = rsqrtf(red[0] * (1.f / CK) + 1e-5f);

    float* out = g_xkv + (size_t)row * CK;
    for (int c = tid; c < CK; c += 256)
        out[c] = (sbuf[c] - mu) * rstd * g[c] + be[c];
}

// ---------------- Generic SGEMM: C[M,N] = A[M,K] @ W[K,N] + bias ----------------
// 128x128x8 tile, 256 threads, 8x8 per thread. M,N multiples of 128; K multiple of 8.
// outMode 0: C[m*ldc + n].  outMode 1: m = b*1024+pix -> C[(b*768+n)*1024 + pix] (BCHW write).
__global__ __launch_bounds__(256) void gemm128(const float* __restrict__ A, int lda,
                                               const float* __restrict__ Bw, int ldb,
                                               const float* __restrict__ bias,
                                               float* __restrict__ C, int ldc,
                                               int K, int outMode)
{
    __shared__ float As[8][128];
    __shared__ float Bs[8][128];

    int tid = threadIdx.x;
    int bm = blockIdx.y * 128;
    int bn = blockIdx.x * 128;
    int tx = tid & 15, ty = tid >> 4;

    int arow = tid >> 1;            // 0..127
    int acol = (tid & 1) * 4;       // 0 or 4
    int brow = tid >> 5;            // 0..7
    int bcol = (tid & 31) * 4;      // 0..124

    const float* Aptr = A + (size_t)(bm + arow) * lda + acol;
    const float* Bptr = Bw + (size_t)brow * ldb + bn + bcol;

    float acc[8][8];
#pragma unroll
    for (int i = 0; i < 8; i++)
#pragma unroll
        for (int j = 0; j < 8; j++) acc[i][j] = 0.f;

    for (int k0 = 0; k0 < K; k0 += 8) {
        float4 av = *(const float4*)(Aptr + k0);
        float4 bv = *(const float4*)(Bptr + (size_t)k0 * ldb);
        As[acol + 0][arow] = av.x;
        As[acol + 1][arow] = av.y;
        As[acol + 2][arow] = av.z;
        As[acol + 3][arow] = av.w;
        *(float4*)&Bs[brow][bcol] = bv;
        __syncthreads();

#pragma unroll
        for (int kk = 0; kk < 8; kk++) {
            float a[8], b[8];
#pragma unroll
            for (int i = 0; i < 4; i++) {
                a[i]     = As[kk][ty * 4 + i];
                a[i + 4] = As[kk][64 + ty * 4 + i];
            }
#pragma unroll
            for (int j = 0; j < 4; j++) {
                b[j]     = Bs[kk][tx * 4 + j];
                b[j + 4] = Bs[kk][64 + tx * 4 + j];
            }
#pragma unroll
            for (int i = 0; i < 8; i++)
#pragma unroll
                for (int j = 0; j < 8; j++) acc[i][j] += a[i] * b[j];
        }
        __syncthreads();
    }

#pragma unroll
    for (int i = 0; i < 8; i++) {
        int m = bm + ((i < 4) ? (ty * 4 + i) : (64 + ty * 4 + (i - 4)));
#pragma unroll
        for (int j = 0; j < 8; j++) {
            int n = bn + ((j < 4) ? (tx * 4 + j) : (64 + tx * 4 + (j - 4)));
            float val = acc[i][j] + bias[n];
            if (outMode == 0) {
                C[(size_t)m * ldc + n] = val;
            } else {
                int b   = m >> 10;
                int pix = m & 1023;
                C[((size_t)b * DQ + n) * HWN + pix] = val;
            }
        }
    }
}

// ---------------- Scores: S[bh][qm][kn] = (q . k) * 0.125 * tw[kn>>10] ----------------
// grid (TKV/64, HW/64, 24), 256 threads, 4x4 per thread, K=64 in one smem pass.
__global__ __launch_bounds__(256) void scores_kernel(const float* __restrict__ tw)
{
    int bh = blockIdx.z;
    int b  = bh / NH;
    int h  = bh % NH;
    int qm0 = blockIdx.y * 64;
    int kn0 = blockIdx.x * 64;

    __shared__ float Qs[64][65];
    __shared__ float Ks[64][65];

    int tid = threadIdx.x;
    for (int e = tid; e < 64 * 64; e += 256) {
        int r = e >> 6, c = e & 63;
        Qs[r][c] = g_q[((size_t)(b * HWN + qm0 + r)) * DQ + h * HD + c];
        Ks[r][c] = g_k[((size_t)(b * TKV + kn0 + r)) * DQ + h * HD + c];
    }
    __syncthreads();

    int tx = tid & 15, ty = tid >> 4;
    float acc[4][4];
#pragma unroll
    for (int i = 0; i < 4; i++)
#pragma unroll
        for (int j = 0; j < 4; j++) acc[i][j] = 0.f;

#pragma unroll 8
    for (int k = 0; k < 64; k++) {
        float a[4], bb[4];
#pragma unroll
        for (int i = 0; i < 4; i++) a[i]  = Qs[ty * 4 + i][k];
#pragma unroll
        for (int j = 0; j < 4; j++) bb[j] = Ks[tx * 4 + j][k];
#pragma unroll
        for (int i = 0; i < 4; i++)
#pragma unroll
            for (int j = 0; j < 4; j++) acc[i][j] += a[i] * bb[j];
    }

    float* Sout = g_s + (size_t)bh * HWN * TKV;
#pragma unroll
    for (int j = 0; j < 4; j++) {
        int kn = kn0 + tx * 4 + j;
        float scale = 0.125f * tw[kn >> 10];
#pragma unroll
        for (int i = 0; i < 4; i++) {
            int qm = qm0 + ty * 4 + i;
            Sout[(size_t)qm * TKV + kn] = acc[i][j] * scale;
        }
    }
}

// ---------------- Row softmax over 4096 keys, in place ----------------
__global__ __launch_bounds__(256) void softmax_kernel()
{
    int row = blockIdx.x;                      // 0..24575 (bh*1024 + q)
    float* p = g_s + (size_t)row * TKV;

    __shared__ float buf[TKV];
    __shared__ float red[256];
    int tid = threadIdx.x;

    float mx = -1e30f;
    for (int c = tid; c < TKV; c += 256) { float v = p[c]; buf[c] = v; mx = fmaxf(mx, v); }
    red[tid] = mx; __syncthreads();
    for (int st = 128; st > 0; st >>= 1) { if (tid < st) red[tid] = fmaxf(red[tid], red[tid + st]); __syncthreads(); }
    mx = red[0];
    __syncthreads();

    float s = 0.f;
    for (int c = tid; c < TKV; c += 256) { float e = __expf(buf[c] - mx); buf[c] = e; s += e; }
    red[tid] = s; __syncthreads();
    for (int st = 128; st > 0; st >>= 1) { if (tid < st) red[tid] += red[tid + st]; __syncthreads(); }
    float inv = 1.f / red[0];

    for (int c = tid; c < TKV; c += 256) p[c] = buf[c] * inv;
}

// ---------------- PV: out[bh][qm][d] = sum_k P[qm][k] * V[k][d], K=4096 ----------------
// grid (HW/64, 1, 24), 256 threads, 64x64 out tile, BK=16.
__global__ __launch_bounds__(256) void pv_kernel()
{
    int bh = blockIdx.z;
    int b  = bh / NH;
    int h  = bh % NH;
    int qm0 = blockIdx.x * 64;

    __shared__ float Ps[16][65];
    __shared__ float Vs[16][65];

    int tid = threadIdx.x;
    int tx = tid & 15, ty = tid >> 4;

    const float* Prow = g_s + (size_t)bh * HWN * TKV + (size_t)qm0 * TKV;

    float acc[4][4];
#pragma unroll
    for (int i = 0; i < 4; i++)
#pragma unroll
        for (int j = 0; j < 4; j++) acc[i][j] = 0.f;

    for (int k0 = 0; k0 < TKV; k0 += 16) {
        for (int e = tid; e < 64 * 16; e += 256) {
            int m = e >> 4, kk = e & 15;
            Ps[kk][m] = Prow[(size_t)m * TKV + k0 + kk];
        }
        for (int e = tid; e < 16 * 64; e += 256) {
            int kk = e >> 6, n = e & 63;
            Vs[kk][n] = g_v[((size_t)(b * TKV + k0 + kk)) * DQ + h * HD + n];
        }
        __syncthreads();

#pragma unroll
        for (int kk = 0; kk < 16; kk++) {
            float a[4], bb[4];
#pragma unroll
            for (int i = 0; i < 4; i++) a[i]  = Ps[kk][ty * 4 + i];
#pragma unroll
            for (int j = 0; j < 4; j++) bb[j] = Vs[kk][tx * 4 + j];
#pragma unroll
            for (int i = 0; i < 4; i++)
#pragma unroll
                for (int j = 0; j < 4; j++) acc[i][j] += a[i] * bb[j];
        }
        __syncthreads();
    }

#pragma unroll
    for (int i = 0; i < 4; i++) {
        int m = qm0 + ty * 4 + i;
#pragma unroll
        for (int j = 0; j < 4; j++) {
            int n = tx * 4 + j;
            g_att[((size_t)(b * HWN + m)) * DQ + h * HD + n] = acc[i][j];
        }
    }
}

// ---------------- Launch ----------------
extern "C" void kernel_launch(void* const* d_in, const int* in_sizes, int n_in,
                              void* d_out, int out_size)
{
    const float* dino = (const float*)d_in[0];
    const float* cog  = (const float*)d_in[1];
    const float* tw   = (const float*)d_in[2];
    const float* Wq   = (const float*)d_in[3];
    const float* bq   = (const float*)d_in[4];
    const float* Wk   = (const float*)d_in[5];
    const float* bk   = (const float*)d_in[6];
    const float* Wv   = (const float*)d_in[7];
    const float* bv   = (const float*)d_in[8];
    const float* Wo   = (const float*)d_in[9];
    const float* bo   = (const float*)d_in[10];
    const float* gq   = (const float*)d_in[11];
    const float* Bq   = (const float*)d_in[12];
    const float* gkv  = (const float*)d_in[13];
    const float* Bkv  = (const float*)d_in[14];
    float* out = (float*)d_out;

    float *p_xq, *p_xkv, *p_q, *p_k, *p_v, *p_att;
    cudaGetSymbolAddress((void**)&p_xq,  g_xq);
    cudaGetSymbolAddress((void**)&p_xkv, g_xkv);
    cudaGetSymbolAddress((void**)&p_q,   g_q);
    cudaGetSymbolAddress((void**)&p_k,   g_k);
    cudaGetSymbolAddress((void**)&p_v,   g_v);
    cudaGetSymbolAddress((void**)&p_att, g_att);

    // 1. LayerNorms
    ln_q_kernel <<<MQ,  256>>>(dino, gq,  Bq);
    ln_kv_kernel<<<MKV, 256>>>(cog,  gkv, Bkv);

    // 2. Projections
    gemm128<<<dim3(DQ/128, MQ/128),  256>>>(p_xq,  DQ, Wq, DQ, bq, p_q, DQ, DQ, 0);
    gemm128<<<dim3(DQ/128, MKV/128), 256>>>(p_xkv, CK, Wk, DQ, bk, p_k, DQ, CK, 0);
    gemm128<<<dim3(DQ/128, MKV/128), 256>>>(p_xkv, CK, Wv, DQ, bv, p_v, DQ, CK, 0);

    // 3. Attention
    scores_kernel <<<dim3(TKV/64, HWN/64, BB*NH), 256>>>(tw);
    softmax_kernel<<<BB*NH*HWN, 256>>>();
    pv_kernel     <<<dim3(HWN/64, 1, BB*NH), 256>>>();

    // 4. Output projection with fused BCHW transpose
    gemm128<<<dim3(DQ/128, MQ/128), 256>>>(p_att, DQ, Wo, DQ, bo, out, DQ, DQ, 1);
}

// round 10
// speedup vs baseline: 1.0017x; 1.0017x over previous
#include <cuda_runtime.h>
#include <math.h>

// ---------------- Problem constants ----------------
#define BB   2
#define TT   4
#define HWN  1024            // H*W
#define TKV  4096            // T*H*W
#define DQ   768             // DINO_DIM
#define CK   1920            // COG_DIM
#define NH   12
#define HD   64
#define MQ   (BB*HWN)        // 2048 query rows
#define MKV  (BB*TKV)        // 8192 kv rows

// ---------------- Scratch (device globals; no allocation APIs) ----------------
__device__ float g_xq [MQ  * DQ];          //  6.3 MB  normalized q input
__device__ float g_xkv[MKV * CK];          // 62.9 MB  normalized kv input
__device__ float g_q  [MQ  * DQ];          //  6.3 MB
__device__ float g_k  [MKV * DQ];          // 25.2 MB
__device__ float g_v  [MKV * DQ];          // 25.2 MB
__device__ float g_s  [(size_t)BB*NH*HWN*TKV]; // 402.7 MB attention scores / probs
__device__ float g_att[MQ  * DQ];          //  6.3 MB

// ---------------- LayerNorm for q path: input [B, 768, 32, 32] ----------------
__global__ __launch_bounds__(256) void ln_q_kernel(const float* __restrict__ x,
                                                   const float* __restrict__ g,
                                                   const float* __restrict__ be)
{
    int row = blockIdx.x;            // 0..2047 = b*1024 + pix
    int b   = row >> 10;
    int pix = row & 1023;
    const float* base = x + (size_t)b * DQ * HWN + pix;   // stride HWN over channels

    __shared__ float sbuf[DQ];
    __shared__ float red[256];
    int tid = threadIdx.x;

    float s = 0.f;
    for (int c = tid; c < DQ; c += 256) {
        float v = base[(size_t)c * HWN];
        sbuf[c] = v;
        s += v;
    }
    red[tid] = s; __syncthreads();
    for (int st = 128; st > 0; st >>= 1) { if (tid < st) red[tid] += red[tid + st]; __syncthreads(); }
    float mu = red[0] * (1.f / DQ);
    __syncthreads();

    float s2 = 0.f;
    for (int c = tid; c < DQ; c += 256) { float d = sbuf[c] - mu; s2 += d * d; }
    red[tid] = s2; __syncthreads();
    for (int st = 128; st > 0; st >>= 1) { if (tid < st) red[tid] += red[tid + st]; __syncthreads(); }
    float rstd = rsqrtf(red[0] * (1.f / DQ) + 1e-5f);

    float* out = g_xq + (size_t)row * DQ;
    for (int c = tid; c < DQ; c += 256)
        out[c] = (sbuf[c] - mu) * rstd * g[c] + be[c];
}

// ---------------- LayerNorm for kv path: input [B,T,H,W,1920] ----------------
__global__ __launch_bounds__(256) void ln_kv_kernel(const float* __restrict__ x,
                                                    const float* __restrict__ g,
                                                    const float* __restrict__ be)
{
    int row = blockIdx.x;            // 0..8191
    const float* base = x + (size_t)row * CK;

    __shared__ float sbuf[CK];
    __shared__ float red[256];
    int tid = threadIdx.x;

    float s = 0.f;
    for (int c = tid; c < CK; c += 256) { float v = base[c]; sbuf[c] = v; s += v; }
    red[tid] = s; __syncthreads();
    for (int st = 128; st > 0; st >>= 1) { if (tid < st) red[tid] += red[tid + st]; __syncthreads(); }
    float mu = red[0] * (1.f / CK);
    __syncthreads();

    float s2 = 0.f;
    for (int c = tid; c < CK; c += 256) { float d = sbuf[c] - mu; s2 += d * d; }
    red[tid] = s2; __syncthreads();
    for (int st = 128; st > 0; st >>= 1) { if (tid < st) red[tid] += red[tid + st]; __syncthreads(); }
    float rstd = rsqrtf(red[0] * (1.f / CK) + 1e-5f);

    float* out = g_xkv + (size_t)row * CK;
    for (int c = tid; c < CK; c += 256)
        out[c] = (sbuf[c] - mu) * rstd * g[c] + be[c];
}

// ---------------- Generic SGEMM: C[M,N] = A[M,K] @ W[K,N] + bias ----------------
// 128x128x8 tile, 256 threads, 8x8 per thread. M,N multiples of 128; K multiple of 8.
// outMode 0: C[m*ldc + n].  outMode 1: m = b*1024+pix -> C[(b*768+n)*1024 + pix] (BCHW write).
__global__ __launch_bounds__(256) void gemm128(const float* __restrict__ A, int lda,
                                               const float* __restrict__ Bw, int ldb,
                                               const float* __restrict__ bias,
                                               float* __restrict__ C, int ldc,
                                               int K, int outMode)
{
    __shared__ float As[8][128];
    __shared__ float Bs[8][128];

    int tid = threadIdx.x;
    int bm = blockIdx.y * 128;
    int bn = blockIdx.x * 128;
    int tx = tid & 15, ty = tid >> 4;

    int arow = tid >> 1;            // 0..127
    int acol = (tid & 1) * 4;       // 0 or 4
    int brow = tid >> 5;            // 0..7
    int bcol = (tid & 31) * 4;      // 0..124

    const float* Aptr = A + (size_t)(bm + arow) * lda + acol;
    const float* Bptr = Bw + (size_t)brow * ldb + bn + bcol;

    float acc[8][8];
#pragma unroll
    for (int i = 0; i < 8; i++)
#pragma unroll
        for (int j = 0; j < 8; j++) acc[i][j] = 0.f;

    for (int k0 = 0; k0 < K; k0 += 8) {
        float4 av = *(const float4*)(Aptr + k0);
        float4 bv = *(const float4*)(Bptr + (size_t)k0 * ldb);
        As[acol + 0][arow] = av.x;
        As[acol + 1][arow] = av.y;
        As[acol + 2][arow] = av.z;
        As[acol + 3][arow] = av.w;
        *(float4*)&Bs[brow][bcol] = bv;
        __syncthreads();

#pragma unroll
        for (int kk = 0; kk < 8; kk++) {
            float a[8], b[8];
#pragma unroll
            for (int i = 0; i < 4; i++) {
                a[i]     = As[kk][ty * 4 + i];
                a[i + 4] = As[kk][64 + ty * 4 + i];
            }
#pragma unroll
            for (int j = 0; j < 4; j++) {
                b[j]     = Bs[kk][tx * 4 + j];
                b[j + 4] = Bs[kk][64 + tx * 4 + j];
            }
#pragma unroll
            for (int i = 0; i < 8; i++)
#pragma unroll
                for (int j = 0; j < 8; j++) acc[i][j] += a[i] * b[j];
        }
        __syncthreads();
    }

#pragma unroll
    for (int i = 0; i < 8; i++) {
        int m = bm + ((i < 4) ? (ty * 4 + i) : (64 + ty * 4 + (i - 4)));
#pragma unroll
        for (int j = 0; j < 8; j++) {
            int n = bn + ((j < 4) ? (tx * 4 + j) : (64 + tx * 4 + (j - 4)));
            float val = acc[i][j] + bias[n];
            if (outMode == 0) {
                C[(size_t)m * ldc + n] = val;
            } else {
                int b   = m >> 10;
                int pix = m & 1023;
                C[((size_t)b * DQ + n) * HWN + pix] = val;
            }
        }
    }
}

// ---------------- Scores: S[bh][qm][kn] = (q . k) * 0.125 * tw[kn>>10] ----------------
// grid (TKV/64, HW/64, 24), 256 threads, 4x4 per thread, K=64 in one smem pass.
__global__ __launch_bounds__(256) void scores_kernel(const float* __restrict__ tw)
{
    int bh = blockIdx.z;
    int b  = bh / NH;
    int h  = bh % NH;
    int qm0 = blockIdx.y * 64;
    int kn0 = blockIdx.x * 64;

    __shared__ float Qs[64][65];
    __shared__ float Ks[64][65];

    int tid = threadIdx.x;
    for (int e = tid; e < 64 * 64; e += 256) {
        int r = e >> 6, c = e & 63;
        Qs[r][c] = g_q[((size_t)(b * HWN + qm0 + r)) * DQ + h * HD + c];
        Ks[r][c] = g_k[((size_t)(b * TKV + kn0 + r)) * DQ + h * HD + c];
    }
    __syncthreads();

    int tx = tid & 15, ty = tid >> 4;
    float acc[4][4];
#pragma unroll
    for (int i = 0; i < 4; i++)
#pragma unroll
        for (int j = 0; j < 4; j++) acc[i][j] = 0.f;

#pragma unroll 8
    for (int k = 0; k < 64; k++) {
        float a[4], bb[4];
#pragma unroll
        for (int i = 0; i < 4; i++) a[i]  = Qs[ty * 4 + i][k];
#pragma unroll
        for (int j = 0; j < 4; j++) bb[j] = Ks[tx * 4 + j][k];
#pragma unroll
        for (int i = 0; i < 4; i++)
#pragma unroll
            for (int j = 0; j < 4; j++) acc[i][j] += a[i] * bb[j];
    }

    float* Sout = g_s + (size_t)bh * HWN * TKV;
#pragma unroll
    for (int j = 0; j < 4; j++) {
        int kn = kn0 + tx * 4 + j;
        float scale = 0.125f * tw[kn >> 10];
#pragma unroll
        for (int i = 0; i < 4; i++) {
            int qm = qm0 + ty * 4 + i;
            Sout[(size_t)qm * TKV + kn] = acc[i][j] * scale;
        }
    }
}

// ---------------- Row softmax over 4096 keys, in place ----------------
__global__ __launch_bounds__(256) void softmax_kernel()
{
    int row = blockIdx.x;                      // 0..24575 (bh*1024 + q)
    float* p = g_s + (size_t)row * TKV;

    __shared__ float buf[TKV];
    __shared__ float red[256];
    int tid = threadIdx.x;

    float mx = -1e30f;
    for (int c = tid; c < TKV; c += 256) { float v = p[c]; buf[c] = v; mx = fmaxf(mx, v); }
    red[tid] = mx; __syncthreads();
    for (int st = 128; st > 0; st >>= 1) { if (tid < st) red[tid] = fmaxf(red[tid], red[tid + st]); __syncthreads(); }
    mx = red[0];
    __syncthreads();

    float s = 0.f;
    for (int c = tid; c < TKV; c += 256) { float e = __expf(buf[c] - mx); buf[c] = e; s += e; }
    red[tid] = s; __syncthreads();
    for (int st = 128; st > 0; st >>= 1) { if (tid < st) red[tid] += red[tid + st]; __syncthreads(); }
    float inv = 1.f / red[0];

    for (int c = tid; c < TKV; c += 256) p[c] = buf[c] * inv;
}

// ---------------- PV: out[bh][qm][d] = sum_k P[qm][k] * V[k][d], K=4096 ----------------
// grid (HW/64, 1, 24), 256 threads, 64x64 out tile, BK=16.
__global__ __launch_bounds__(256) void pv_kernel()
{
    int bh = blockIdx.z;
    int b  = bh / NH;
    int h  = bh % NH;
    int qm0 = blockIdx.x * 64;

    __shared__ float Ps[16][65];
    __shared__ float Vs[16][65];

    int tid = threadIdx.x;
    int tx = tid & 15, ty = tid >> 4;

    const float* Prow = g_s + (size_t)bh * HWN * TKV + (size_t)qm0 * TKV;

    float acc[4][4];
#pragma unroll
    for (int i = 0; i < 4; i++)
#pragma unroll
        for (int j = 0; j < 4; j++) acc[i][j] = 0.f;

    for (int k0 = 0; k0 < TKV; k0 += 16) {
        for (int e = tid; e < 64 * 16; e += 256) {
            int m = e >> 4, kk = e & 15;
            Ps[kk][m] = Prow[(size_t)m * TKV + k0 + kk];
        }
        for (int e = tid; e < 16 * 64; e += 256) {
            int kk = e >> 6, n = e & 63;
            Vs[kk][n] = g_v[((size_t)(b * TKV + k0 + kk)) * DQ + h * HD + n];
        }
        __syncthreads();

#pragma unroll
        for (int kk = 0; kk < 16; kk++) {
            float a[4], bb[4];
#pragma unroll
            for (int i = 0; i < 4; i++) a[i]  = Ps[kk][ty * 4 + i];
#pragma unroll
            for (int j = 0; j < 4; j++) bb[j] = Vs[kk][tx * 4 + j];
#pragma unroll
            for (int i = 0; i < 4; i++)
#pragma unroll
                for (int j = 0; j < 4; j++) acc[i][j] += a[i] * bb[j];
        }
        __syncthreads();
    }

#pragma unroll
    for (int i = 0; i < 4; i++) {
        int m = qm0 + ty * 4 + i;
#pragma unroll
        for (int j = 0; j < 4; j++) {
            int n = tx * 4 + j;
            g_att[((size_t)(b * HWN + m)) * DQ + h * HD + n] = acc[i][j];
        }
    }
}

// ---------------- Launch ----------------
extern "C" void kernel_launch(void* const* d_in, const int* in_sizes, int n_in,
                              void* d_out, int out_size)
{
    const float* dino = (const float*)d_in[0];
    const float* cog  = (const float*)d_in[1];
    const float* tw   = (const float*)d_in[2];
    const float* Wq   = (const float*)d_in[3];
    const float* bq   = (const float*)d_in[4];
    const float* Wk   = (const float*)d_in[5];
    const float* bk   = (const float*)d_in[6];
    const float* Wv   = (const float*)d_in[7];
    const float* bv   = (const float*)d_in[8];
    const float* Wo   = (const float*)d_in[9];
    const float* bo   = (const float*)d_in[10];
    const float* gq   = (const float*)d_in[11];
    const float* Bq   = (const float*)d_in[12];
    const float* gkv  = (const float*)d_in[13];
    const float* Bkv  = (const float*)d_in[14];
    float* out = (float*)d_out;

    float *p_xq, *p_xkv, *p_q, *p_k, *p_v, *p_att;
    cudaGetSymbolAddress((void**)&p_xq,  g_xq);
    cudaGetSymbolAddress((void**)&p_xkv, g_xkv);
    cudaGetSymbolAddress((void**)&p_q,   g_q);
    cudaGetSymbolAddress((void**)&p_k,   g_k);
    cudaGetSymbolAddress((void**)&p_v,   g_v);
    cudaGetSymbolAddress((void**)&p_att, g_att);

    // 1. LayerNorms
    ln_q_kernel <<<MQ,  256>>>(dino, gq,  Bq);
    ln_kv_kernel<<<MKV, 256>>>(cog,  gkv, Bkv);

    // 2. Projections
    gemm128<<<dim3(DQ/128, MQ/128),  256>>>(p_xq,  DQ, Wq, DQ, bq, p_q, DQ, DQ, 0);
    gemm128<<<dim3(DQ/128, MKV/128), 256>>>(p_xkv, CK, Wk, DQ, bk, p_k, DQ, CK, 0);
    gemm128<<<dim3(DQ/128, MKV/128), 256>>>(p_xkv, CK, Wv, DQ, bv, p_v, DQ, CK, 0);

    // 3. Attention
    scores_kernel <<<dim3(TKV/64, HWN/64, BB*NH), 256>>>(tw);
    softmax_kernel<<<BB*NH*HWN, 256>>>();
    pv_kernel     <<<dim3(HWN/64, 1, BB*NH), 256>>>();

    // 4. Output projection with fused BCHW transpose
    gemm128<<<dim3(DQ/128, MQ/128), 256>>>(p_att, DQ, Wo, DQ, bo, out, DQ, DQ, 1);
}